// round 16
// baseline (speedup 1.0000x reference)
#include <cuda_runtime.h>
#include <cuda_fp16.h>
#include <math.h>
#include <stdint.h>

#define NN   50000
#define EE   400000
#define F_IN 128
#define HH   3
#define DD   64
#define HD   192
#define GG   64
#define PP   64
#define NEG_GAT 0.2f
#define NEG  0.01f

// ---------------- device scratch ----------------
__device__ __align__(16) __half g_fsh[(size_t)NN * HD];        // fc_src feats (fp16)
__device__ __align__(16) __half g_fdh[(size_t)NN * HD];        // fc_dst feats (fp16)
__device__ __align__(16) __half g_x[(size_t)NN * HD];          // activations (fp16)
__device__ __align__(16) __half g_w[3 * (size_t)HD * 384];     // per-layer weights (fp16)
__device__ int g_deg[NN];
__device__ int g_rowptr[NN + 1];
__device__ int g_cur[NN];
__device__ int g_esrc[EE];
__device__ float g_pool[GG * DD];
__device__ float g_cnt[GG];

// ---------------- PTX helpers ----------------
__device__ __forceinline__ uint32_t cvta_shared_u32(const void* p) {
    uint32_t a;
    asm("{ .reg .u64 t; cvta.to.shared.u64 t, %1; cvt.u32.u64 %0, t; }" : "=r"(a) : "l"(p));
    return a;
}
__device__ __forceinline__ void cpasync16(uint32_t smem, const void* g, int srcsize) {
    asm volatile("cp.async.cg.shared.global [%0], [%1], 16, %2;"
                 :: "r"(smem), "l"(g), "r"(srcsize) : "memory");
}
__device__ __forceinline__ void cp_commit() {
    asm volatile("cp.async.commit_group;" ::: "memory");
}
template <int N> __device__ __forceinline__ void cp_wait() {
    asm volatile("cp.async.wait_group %0;" :: "n"(N) : "memory");
}
__device__ __forceinline__ void ldsm4(uint32_t* r, uint32_t addr) {
    asm volatile("ldmatrix.sync.aligned.m8n8.x4.shared.b16 {%0,%1,%2,%3}, [%4];"
                 : "=r"(r[0]), "=r"(r[1]), "=r"(r[2]), "=r"(r[3]) : "r"(addr));
}
__device__ __forceinline__ void ldsm4t(uint32_t* r, uint32_t addr) {
    asm volatile("ldmatrix.sync.aligned.m8n8.x4.trans.shared.b16 {%0,%1,%2,%3}, [%4];"
                 : "=r"(r[0]), "=r"(r[1]), "=r"(r[2]), "=r"(r[3]) : "r"(addr));
}
__device__ __forceinline__ void mma16816f16(float* c, const uint32_t* a, const uint32_t* b) {
    asm volatile("mma.sync.aligned.m16n8k16.row.col.f32.f16.f16.f32 "
                 "{%0,%1,%2,%3}, {%4,%5,%6,%7}, {%8,%9}, {%0,%1,%2,%3};"
                 : "+f"(c[0]), "+f"(c[1]), "+f"(c[2]), "+f"(c[3])
                 : "r"(a[0]), "r"(a[1]), "r"(a[2]), "r"(a[3]), "r"(b[0]), "r"(b[1]));
}

// ---------------- init: pool zero + degree zero (merged) ----------------
__global__ void init_zero_kernel() {
    int i = blockIdx.x * blockDim.x + threadIdx.x;
    if (i < GG * DD) g_pool[i] = 0.f;
    if (i < GG) g_cnt[i] = 0.f;
    if (i < NN) g_deg[i] = 0;
}

// ---------------- CSR build ----------------
__global__ void hist_kernel(const int* __restrict__ dst) {
    int e = blockIdx.x * blockDim.x + threadIdx.x;
    if (e < EE) atomicAdd(&g_deg[dst[e]], 1);
}
__global__ void scan_kernel() {
    __shared__ int sp[1024];
    int tid = threadIdx.x;
    int start = tid * 49;
    int end = start + 49; if (end > NN) end = NN;
    int loc = 0;
    for (int i = start; i < end; i++) loc += g_deg[i];
    sp[tid] = loc;
    __syncthreads();
    for (int off = 1; off < 1024; off <<= 1) {
        int v = (tid >= off) ? sp[tid - off] : 0;
        __syncthreads();
        sp[tid] += v;
        __syncthreads();
    }
    int run = sp[tid] - loc;
    for (int i = start; i < end; i++) {
        g_rowptr[i] = run; g_cur[i] = run; run += g_deg[i];
    }
    if (tid == 1023) g_rowptr[NN] = run;
}
__global__ void scatter_kernel(const int* __restrict__ src, const int* __restrict__ dst) {
    int e = blockIdx.x * blockDim.x + threadIdx.x;
    if (e >= EE) return;
    int pos = atomicAdd(&g_cur[dst[e]], 1);
    g_esrc[pos] = src[e];
}

// ---------------- operand conversions (fp16) ----------------
__global__ void convert_x_kernel(const float* __restrict__ x) {
    int idx = blockIdx.x * blockDim.x + threadIdx.x;
    if (idx >= NN * F_IN / 4) return;
    float4 v = reinterpret_cast<const float4*>(x)[idx];
    __half2* oh = reinterpret_cast<__half2*>(g_x);
    oh[idx * 2]     = __float22half2_rn(make_float2(v.x, v.y));
    oh[idx * 2 + 1] = __float22half2_rn(make_float2(v.z, v.w));
}
__global__ void convert_w_all_kernel(
        const float* __restrict__ W1s, const float* __restrict__ W1d,
        const float* __restrict__ W2s, const float* __restrict__ W2d,
        const float* __restrict__ W3s, const float* __restrict__ W3d) {
    int idx = blockIdx.x * blockDim.x + threadIdx.x;
    int total = (F_IN + HD + HD) * 384;
    if (idx >= total) return;
    int layer, k, base;
    if (idx < F_IN * 384)              { layer = 0; base = idx;                 k = base / 384; }
    else if (idx < (F_IN + HD) * 384)  { layer = 1; base = idx - F_IN * 384;    k = base / 384; }
    else                               { layer = 2; base = idx - (F_IN+HD)*384; k = base / 384; }
    int n = base % 384;
    const float* Ws = layer == 0 ? W1s : (layer == 1 ? W2s : W3s);
    const float* Wd = layer == 0 ? W1d : (layer == 1 ? W2d : W3d);
    float w = (n < HD) ? Ws[(size_t)k * HD + n] : Wd[(size_t)k * HD + n - HD];
    g_w[(size_t)layer * HD * 384 + (size_t)k * 384 + n] = __float2half(w);
}

// ---------------- fp16 mma.sync GEMM, 3-stage cp.async pipeline ------------------
#define SB_OFF 10240
#define STAGE_BYTES 18944
#define GEMM_SMEM (3 * STAGE_BYTES)

__global__ __launch_bounds__(256, 3) void gemm_mma_kernel(int K, size_t woff) {
    extern __shared__ char smdyn[];
    uint32_t smb = cvta_shared_u32(smdyn);
    int tid = threadIdx.x, lane = tid & 31;
    int wid = tid >> 5, wr = wid & 1, wc = wid >> 1;
    int row0 = blockIdx.x * 128, col0 = blockIdx.y * 128;
    int nk = K >> 5;
    const __half* wp = g_w + woff;

    float c[4][4][4];
#pragma unroll
    for (int i = 0; i < 4; i++)
#pragma unroll
        for (int j = 0; j < 4; j++)
#pragma unroll
            for (int k = 0; k < 4; k++) c[i][j][k] = 0.f;

    auto issue = [&](int t) {
        int k0 = t << 5;
        uint32_t sb = smb + (t % 3) * STAGE_BYTES;
#pragma unroll
        for (int h = 0; h < 2; h++) {
            int cc = tid + h * 256;
            int ar = cc >> 2, acg = (cc & 3) << 3;
            int grow = row0 + ar;
            int ok = (grow < NN) ? 16 : 0;
            const __half* pa = ok ? (g_x + (size_t)grow * K + k0 + acg) : g_x;
            cpasync16(sb + ar * 80 + (acg << 1), pa, ok);
            int br = cc >> 4, bcg = (cc & 15) << 3;
            const __half* pb = wp + (size_t)(k0 + br) * 384 + col0 + bcg;
            cpasync16(sb + SB_OFF + br * 272 + (bcg << 1), pb, 16);
        }
        cp_commit();
    };

    issue(0);
    issue(1);

    const int arow = wr * 64 + (lane & 15);
    const int acol = (lane >> 4) << 3;
    const int krow = (lane & 15);
    const int ncll = wc * 32 + ((lane >> 4) << 3);

    for (int t = 0; t < nk; t++) {
        if (t + 1 < nk) cp_wait<1>(); else cp_wait<0>();
        __syncthreads();
        if (t + 2 < nk) issue(t + 2);
        uint32_t sb = smb + (t % 3) * STAGE_BYTES;
#pragma unroll
        for (int ks = 0; ks < 2; ks++) {
            uint32_t Ah[4][4], B[4][2];
#pragma unroll
            for (int mt = 0; mt < 4; mt++)
                ldsm4(Ah[mt], sb + (arow + mt * 16) * 80 + ((ks * 16 + acol) << 1));
            uint32_t bk = sb + SB_OFF + (ks * 16 + krow) * 272;
#pragma unroll
            for (int np = 0; np < 2; np++) {
                uint32_t r[4];
                ldsm4t(r, bk + ((ncll + np * 16) << 1));
                B[2*np][0] = r[0]; B[2*np][1] = r[1];
                B[2*np+1][0] = r[2]; B[2*np+1][1] = r[3];
            }
#pragma unroll
            for (int mt = 0; mt < 4; mt++)
#pragma unroll
                for (int nt = 0; nt < 4; nt++) mma16816f16(c[mt][nt], Ah[mt], B[nt]);
        }
    }

    // epilogue: fs columns -> g_fsh (fp16), fd columns -> g_fdh (fp16)
    int gid4 = lane >> 2, tig = lane & 3;
#pragma unroll
    for (int mt = 0; mt < 4; mt++) {
        int rg = row0 + wr * 64 + mt * 16 + gid4;
#pragma unroll
        for (int nt = 0; nt < 4; nt++) {
            int col = col0 + wc * 32 + nt * 8 + tig * 2;
            __half* base = (col < HD) ? (g_fsh + col) : (g_fdh + (col - HD));
            __half2 v0 = __float22half2_rn(make_float2(c[mt][nt][0], c[mt][nt][1]));
            __half2 v1 = __float22half2_rn(make_float2(c[mt][nt][2], c[mt][nt][3]));
            if (rg < NN)
                *reinterpret_cast<__half2*>(base + (size_t)rg * HD) = v0;
            if (rg + 8 < NN)
                *reinterpret_cast<__half2*>(base + (size_t)(rg + 8) * HD) = v1;
        }
    }
}

// ---------------- fused single-pass GATv2: one warp per node, 2-edge ILP ----------
// Frozen structure; fp16 gathers; half2-packed logit reduction.
__device__ __forceinline__ void edge_logits(
        int s, int lane,
        const float2* va, const float2* vd,
        float2* u, float* l) {
    const __half2* fs2 = reinterpret_cast<const __half2*>(g_fsh + (size_t)s * HD);
    u[0] = __half22float2(__ldg(fs2 + lane));
    u[1] = __half22float2(__ldg(fs2 + lane + 32));
    u[2] = __half22float2(__ldg(fs2 + lane + 64));
    float x, y;
    x = u[0].x + vd[0].x; x = x > 0.f ? x : NEG_GAT * x;
    y = u[0].y + vd[0].y; y = y > 0.f ? y : NEG_GAT * y;
    l[0] = x * va[0].x + y * va[0].y;
    x = u[1].x + vd[1].x; x = x > 0.f ? x : NEG_GAT * x;
    y = u[1].y + vd[1].y; y = y > 0.f ? y : NEG_GAT * y;
    l[1] = x * va[1].x + y * va[1].y;
    x = u[2].x + vd[2].x; x = x > 0.f ? x : NEG_GAT * x;
    y = u[2].y + vd[2].y; y = y > 0.f ? y : NEG_GAT * y;
    l[2] = x * va[2].x + y * va[2].y;
}

__global__ __launch_bounds__(256, 4) void gat_node_kernel(
        const float* __restrict__ attn,
        const float* __restrict__ bias,
        int do_pool, const int* __restrict__ gid) {
    int gw = (blockIdx.x * blockDim.x + threadIdx.x) >> 5;
    if (gw >= NN) return;
    int lane = threadIdx.x & 31;
    int n = gw;
    int p0 = __ldg(g_rowptr + n), p1 = __ldg(g_rowptr + n + 1);

    const float2* a2  = reinterpret_cast<const float2*>(attn);
    const __half2* fd2 = reinterpret_cast<const __half2*>(g_fdh + (size_t)n * HD);
    float2 va[3] = {a2[lane], a2[lane + 32], a2[lane + 64]};
    float2 vd[3] = {__half22float2(fd2[lane]),
                    __half22float2(fd2[lane + 32]),
                    __half22float2(fd2[lane + 64])};

    float den0 = 0.f, den1 = 0.f, den2 = 0.f;
    float2 acc0 = make_float2(0.f, 0.f), acc1 = acc0, acc2 = acc0;

    int p = p0;
    for (; p + 1 < p1; p += 2) {
        int sA = __ldg(g_esrc + p), sB = __ldg(g_esrc + p + 1);
        float2 uA[3], uB[3];
        float lA[3], lB[3];
        edge_logits(sA, lane, va, vd, uA, lA);
        edge_logits(sB, lane, va, vd, uB, lB);
        uint32_t pk[3];
#pragma unroll
        for (int h = 0; h < 3; h++) {
            __half2 v = __floats2half2_rn(lA[h], lB[h]);
            pk[h] = *reinterpret_cast<uint32_t*>(&v);
        }
#pragma unroll
        for (int o = 16; o; o >>= 1) {
#pragma unroll
            for (int h = 0; h < 3; h++) {
                uint32_t ot = __shfl_xor_sync(0xffffffffu, pk[h], o);
                __half2 s = __hadd2(*reinterpret_cast<__half2*>(&pk[h]),
                                    *reinterpret_cast<__half2*>(&ot));
                pk[h] = *reinterpret_cast<uint32_t*>(&s);
            }
        }
        float eA[3], eB[3];
#pragma unroll
        for (int h = 0; h < 3; h++) {
            float2 lf = __half22float2(*reinterpret_cast<__half2*>(&pk[h]));
            eA[h] = __expf(lf.x);
            eB[h] = __expf(lf.y);
        }
        den0 += eA[0] + eB[0]; den1 += eA[1] + eB[1]; den2 += eA[2] + eB[2];
        acc0.x += eA[0] * uA[0].x + eB[0] * uB[0].x; acc0.y += eA[0] * uA[0].y + eB[0] * uB[0].y;
        acc1.x += eA[1] * uA[1].x + eB[1] * uB[1].x; acc1.y += eA[1] * uA[1].y + eB[1] * uB[1].y;
        acc2.x += eA[2] * uA[2].x + eB[2] * uB[2].x; acc2.y += eA[2] * uA[2].y + eB[2] * uB[2].y;
    }
    if (p < p1) {
        int s = __ldg(g_esrc + p);
        float2 u[3];
        float l[3];
        edge_logits(s, lane, va, vd, u, l);
#pragma unroll
        for (int o = 16; o; o >>= 1) {
            l[0] += __shfl_xor_sync(0xffffffffu, l[0], o);
            l[1] += __shfl_xor_sync(0xffffffffu, l[1], o);
            l[2] += __shfl_xor_sync(0xffffffffu, l[2], o);
        }
        float e0 = __expf(l[0]), e1 = __expf(l[1]), e2 = __expf(l[2]);
        den0 += e0; den1 += e1; den2 += e2;
        acc0.x += e0 * u[0].x; acc0.y += e0 * u[0].y;
        acc1.x += e1 * u[1].x; acc1.y += e1 * u[1].y;
        acc2.x += e2 * u[2].x; acc2.y += e2 * u[2].y;
    }

    float i0 = 1.f / fmaxf(den0, 1e-9f);
    float i1 = 1.f / fmaxf(den1, 1e-9f);
    float i2 = 1.f / fmaxf(den2, 1e-9f);

    const float2* b2 = reinterpret_cast<const float2*>(bias);
    float2 w0 = b2[lane], w1 = b2[lane + 32], w2 = b2[lane + 64];
    float2 o0 = make_float2(acc0.x * i0 + w0.x, acc0.y * i0 + w0.y);
    float2 o1 = make_float2(acc1.x * i1 + w1.x, acc1.y * i1 + w1.y);
    float2 o2 = make_float2(acc2.x * i2 + w2.x, acc2.y * i2 + w2.y);

    if (!do_pool) {
        __half2* oh = reinterpret_cast<__half2*>(g_x + (size_t)n * HD);
        oh[lane]      = __float22half2_rn(o0);
        oh[lane + 32] = __float22half2_rn(o1);
        oh[lane + 64] = __float22half2_rn(o2);
    } else {
        int g = __ldg(gid + n);
        float vx = (o0.x + o1.x + o2.x) * (1.f / 3.f);
        float vy = (o0.y + o1.y + o2.y) * (1.f / 3.f);
        atomicAdd(&g_pool[g * DD + 2 * lane], vx);
        atomicAdd(&g_pool[g * DD + 2 * lane + 1], vy);
        if (lane == 0) atomicAdd(&g_cnt[g], 1.f);
    }
}

// ---------------- pattern branch + classifier head ----------------
__global__ void head_kernel(const float* __restrict__ p1, const float* __restrict__ p2,
                            const float* __restrict__ p3,
                            const float* __restrict__ Wex, const float* __restrict__ bex,
                            const float* __restrict__ Wpat, const float* __restrict__ bpat,
                            const float* __restrict__ Wc1, const float* __restrict__ bc1,
                            const float* __restrict__ Wc2, const float* __restrict__ bc2,
                            const float* __restrict__ Wc3, const float* __restrict__ bc3,
                            float* __restrict__ outp) {
    __shared__ float s_px[GG * 96];
    __shared__ float s_pat[GG * 64];
    int tid = threadIdx.x;

    for (int idx = tid; idx < GG * 96; idx += 256) {
        int g = idx / 96, j = idx % 96;
        const float* p = (j < 32) ? p1 : (j < 64 ? p2 : p3);
        int jj = j & 31;
        float s = bex[jj];
        for (int k = 0; k < PP; k++) s += p[g * PP + k] * Wex[k * 32 + jj];
        s_px[idx] = s;
    }
    __syncthreads();
    for (int idx = tid; idx < GG * 64; idx += 256) {
        int g = idx >> 6, j = idx & 63;
        float s = bpat[j];
        for (int k = 0; k < 96; k++) s += s_px[g * 96 + k] * Wpat[k * 64 + j];
        s_pat[idx] = s > 0.f ? s : NEG * s;
    }
    __syncthreads();
    for (int idx = tid; idx < GG * 64; idx += 256) {
        int g = idx >> 6, j = idx & 63;
        float s = bc1[j];
        float inv = 1.f / fmaxf(g_cnt[g], 1.f);
        for (int k = 0; k < 64; k++) s += (g_pool[g * 64 + k] * inv) * Wc1[k * 64 + j];
        for (int k = 0; k < 64; k++) s += s_pat[g * 64 + k] * Wc1[(64 + k) * 64 + j];
        s_px[idx] = s > 0.f ? s : NEG * s;
    }
    __syncthreads();
    for (int idx = tid; idx < GG * 32; idx += 256) {
        int g = idx >> 5, j = idx & 31;
        float s = bc2[j];
        for (int k = 0; k < 64; k++) s += s_px[g * 64 + k] * Wc2[k * 32 + j];
        s_px[4096 + idx] = s > 0.f ? s : NEG * s;
    }
    __syncthreads();
    for (int idx = tid; idx < GG * 2; idx += 256) {
        int g = idx >> 1, j = idx & 1;
        float s = bc3[j];
        for (int k = 0; k < 32; k++) s += s_px[4096 + g * 32 + k] * Wc3[k * 2 + j];
        outp[idx] = s;
    }
}

// ---------------- launcher ----------------
extern "C" void kernel_launch(void* const* d_in, const int* in_sizes, int n_in,
                              void* d_out, int out_size) {
    const float* x_in = (const float*)d_in[0];
    const int*   src  = (const int*)d_in[1];
    const int*   dst  = (const int*)d_in[2];
    const int*   gid  = (const int*)d_in[3];
    const float* p1   = (const float*)d_in[4];
    const float* p2   = (const float*)d_in[5];
    const float* p3   = (const float*)d_in[6];
    const float* W1s = (const float*)d_in[7],  *W1d = (const float*)d_in[8];
    const float* a1  = (const float*)d_in[9],  *b1  = (const float*)d_in[10];
    const float* W2s = (const float*)d_in[11], *W2d = (const float*)d_in[12];
    const float* a2  = (const float*)d_in[13], *b2  = (const float*)d_in[14];
    const float* W3s = (const float*)d_in[15], *W3d = (const float*)d_in[16];
    const float* a3  = (const float*)d_in[17], *b3  = (const float*)d_in[18];
    const float* Wex = (const float*)d_in[19], *bex = (const float*)d_in[20];
    const float* Wpat= (const float*)d_in[21], *bpat= (const float*)d_in[22];
    const float* Wc1 = (const float*)d_in[23], *bc1 = (const float*)d_in[24];
    const float* Wc2 = (const float*)d_in[25], *bc2 = (const float*)d_in[26];
    const float* Wc3 = (const float*)d_in[27], *bc3 = (const float*)d_in[28];

    cudaFuncSetAttribute(gemm_mma_kernel, cudaFuncAttributeMaxDynamicSharedMemorySize, GEMM_SMEM);

    dim3 gemm_grid((NN + 127) / 128, 3);       // (391, 3)
    int  node_blocks = (NN * 32 + 255) / 256;  // 6250
    size_t wstride = (size_t)HD * 384;

    // Launch order: profiled slot (4th) = gemm_mma (layer 1).
    init_zero_kernel<<<(NN + 255) / 256, 256>>>();                        // 1
    convert_x_kernel<<<(NN * F_IN / 4 + 255) / 256, 256>>>(x_in);         // 2
    convert_w_all_kernel<<<((F_IN + 2 * HD) * 384 + 255) / 256, 256>>>(
        W1s, W1d, W2s, W2d, W3s, W3d);                                    // 3
    gemm_mma_kernel<<<gemm_grid, 256, GEMM_SMEM>>>(F_IN, 0);              // 4 <- ncu slot

    // CSR build (needed only by gat kernels)
    hist_kernel<<<(EE + 255) / 256, 256>>>(dst);
    scan_kernel<<<1, 1024>>>();
    scatter_kernel<<<(EE + 255) / 256, 256>>>(src, dst);

    gat_node_kernel<<<node_blocks, 256>>>(a1, b1, 0, gid);

    // ---- Layer 2 (K = 192)
    gemm_mma_kernel<<<gemm_grid, 256, GEMM_SMEM>>>(HD, wstride);
    gat_node_kernel<<<node_blocks, 256>>>(a2, b2, 0, gid);

    // ---- Layer 3 (pooling fused)
    gemm_mma_kernel<<<gemm_grid, 256, GEMM_SMEM>>>(HD, 2 * wstride);
    gat_node_kernel<<<node_blocks, 256>>>(a3, b3, 1, gid);

    // ---- head
    head_kernel<<<1, 256>>>(p1, p2, p3, Wex, bex, Wpat, bpat,
                            Wc1, bc1, Wc2, bc2, Wc3, bc3, (float*)d_out);
}

// round 17
// speedup vs baseline: 1.0519x; 1.0519x over previous
#include <cuda_runtime.h>
#include <cuda_fp16.h>
#include <math.h>
#include <stdint.h>

#define NN   50000
#define EE   400000
#define F_IN 128
#define HH   3
#define DD   64
#define HD   192
#define GG   64
#define PP   64
#define NEG_GAT 0.2f
#define NEG  0.01f

// ---------------- device scratch ----------------
__device__ __align__(16) __half g_fsh[(size_t)NN * HD];        // fc_src feats (fp16)
__device__ __align__(16) __half g_fdh[(size_t)NN * HD];        // fc_dst feats (fp16)
__device__ __align__(16) __half g_x[(size_t)NN * HD];          // activations (fp16)
__device__ __align__(16) __half g_w[3 * (size_t)HD * 384];     // per-layer weights (fp16)
__device__ int g_deg[NN];
__device__ int g_rowptr[NN + 1];
__device__ int g_cur[NN];
__device__ int g_esrc[EE];
__device__ float g_pool[GG * DD];
__device__ float g_cnt[GG];

// ---------------- PTX helpers ----------------
__device__ __forceinline__ uint32_t cvta_shared_u32(const void* p) {
    uint32_t a;
    asm("{ .reg .u64 t; cvta.to.shared.u64 t, %1; cvt.u32.u64 %0, t; }" : "=r"(a) : "l"(p));
    return a;
}
__device__ __forceinline__ void cpasync16(uint32_t smem, const void* g, int srcsize) {
    asm volatile("cp.async.cg.shared.global [%0], [%1], 16, %2;"
                 :: "r"(smem), "l"(g), "r"(srcsize) : "memory");
}
__device__ __forceinline__ void cp_commit() {
    asm volatile("cp.async.commit_group;" ::: "memory");
}
template <int N> __device__ __forceinline__ void cp_wait() {
    asm volatile("cp.async.wait_group %0;" :: "n"(N) : "memory");
}
__device__ __forceinline__ void ldsm4(uint32_t* r, uint32_t addr) {
    asm volatile("ldmatrix.sync.aligned.m8n8.x4.shared.b16 {%0,%1,%2,%3}, [%4];"
                 : "=r"(r[0]), "=r"(r[1]), "=r"(r[2]), "=r"(r[3]) : "r"(addr));
}
__device__ __forceinline__ void ldsm4t(uint32_t* r, uint32_t addr) {
    asm volatile("ldmatrix.sync.aligned.m8n8.x4.trans.shared.b16 {%0,%1,%2,%3}, [%4];"
                 : "=r"(r[0]), "=r"(r[1]), "=r"(r[2]), "=r"(r[3]) : "r"(addr));
}
__device__ __forceinline__ void mma16816f16(float* c, const uint32_t* a, const uint32_t* b) {
    asm volatile("mma.sync.aligned.m16n8k16.row.col.f32.f16.f16.f32 "
                 "{%0,%1,%2,%3}, {%4,%5,%6,%7}, {%8,%9}, {%0,%1,%2,%3};"
                 : "+f"(c[0]), "+f"(c[1]), "+f"(c[2]), "+f"(c[3])
                 : "r"(a[0]), "r"(a[1]), "r"(a[2]), "r"(a[3]), "r"(b[0]), "r"(b[1]));
}

// ---------------- init: pool zero + degree zero (merged) ----------------
__global__ void init_zero_kernel() {
    int i = blockIdx.x * blockDim.x + threadIdx.x;
    if (i < GG * DD) g_pool[i] = 0.f;
    if (i < GG) g_cnt[i] = 0.f;
    if (i < NN) g_deg[i] = 0;
}

// ---------------- CSR build ----------------
__global__ void hist_kernel(const int* __restrict__ dst) {
    int e = blockIdx.x * blockDim.x + threadIdx.x;
    if (e < EE) atomicAdd(&g_deg[dst[e]], 1);
}
__global__ void scan_kernel() {
    __shared__ int sp[1024];
    int tid = threadIdx.x;
    int start = tid * 49;
    int end = start + 49; if (end > NN) end = NN;
    int loc = 0;
    for (int i = start; i < end; i++) loc += g_deg[i];
    sp[tid] = loc;
    __syncthreads();
    for (int off = 1; off < 1024; off <<= 1) {
        int v = (tid >= off) ? sp[tid - off] : 0;
        __syncthreads();
        sp[tid] += v;
        __syncthreads();
    }
    int run = sp[tid] - loc;
    for (int i = start; i < end; i++) {
        g_rowptr[i] = run; g_cur[i] = run; run += g_deg[i];
    }
    if (tid == 1023) g_rowptr[NN] = run;
}
__global__ void scatter_kernel(const int* __restrict__ src, const int* __restrict__ dst) {
    int e = blockIdx.x * blockDim.x + threadIdx.x;
    if (e >= EE) return;
    int pos = atomicAdd(&g_cur[dst[e]], 1);
    g_esrc[pos] = src[e];
}

// ---------------- operand conversions (fp16) ----------------
__global__ void convert_x_kernel(const float* __restrict__ x) {
    int idx = blockIdx.x * blockDim.x + threadIdx.x;
    if (idx >= NN * F_IN / 4) return;
    float4 v = reinterpret_cast<const float4*>(x)[idx];
    __half2* oh = reinterpret_cast<__half2*>(g_x);
    oh[idx * 2]     = __float22half2_rn(make_float2(v.x, v.y));
    oh[idx * 2 + 1] = __float22half2_rn(make_float2(v.z, v.w));
}
__global__ void convert_w_all_kernel(
        const float* __restrict__ W1s, const float* __restrict__ W1d,
        const float* __restrict__ W2s, const float* __restrict__ W2d,
        const float* __restrict__ W3s, const float* __restrict__ W3d) {
    int idx = blockIdx.x * blockDim.x + threadIdx.x;
    int total = (F_IN + HD + HD) * 384;
    if (idx >= total) return;
    int layer, k, base;
    if (idx < F_IN * 384)              { layer = 0; base = idx;                 k = base / 384; }
    else if (idx < (F_IN + HD) * 384)  { layer = 1; base = idx - F_IN * 384;    k = base / 384; }
    else                               { layer = 2; base = idx - (F_IN+HD)*384; k = base / 384; }
    int n = base % 384;
    const float* Ws = layer == 0 ? W1s : (layer == 1 ? W2s : W3s);
    const float* Wd = layer == 0 ? W1d : (layer == 1 ? W2d : W3d);
    float w = (n < HD) ? Ws[(size_t)k * HD + n] : Wd[(size_t)k * HD + n - HD];
    g_w[(size_t)layer * HD * 384 + (size_t)k * 384 + n] = __float2half(w);
}

// ---------------- fp16 mma.sync GEMM, 3-stage cp.async pipeline ------------------
#define SB_OFF 10240
#define STAGE_BYTES 18944
#define GEMM_SMEM (3 * STAGE_BYTES)

__global__ __launch_bounds__(256) void gemm_mma_kernel(int K, size_t woff) {
    extern __shared__ char smdyn[];
    uint32_t smb = cvta_shared_u32(smdyn);
    int tid = threadIdx.x, lane = tid & 31;
    int wid = tid >> 5, wr = wid & 1, wc = wid >> 1;
    int row0 = blockIdx.x * 128, col0 = blockIdx.y * 128;
    int nk = K >> 5;
    const __half* wp = g_w + woff;

    float c[4][4][4];
#pragma unroll
    for (int i = 0; i < 4; i++)
#pragma unroll
        for (int j = 0; j < 4; j++)
#pragma unroll
            for (int k = 0; k < 4; k++) c[i][j][k] = 0.f;

    auto issue = [&](int t) {
        int k0 = t << 5;
        uint32_t sb = smb + (t % 3) * STAGE_BYTES;
#pragma unroll
        for (int h = 0; h < 2; h++) {
            int cc = tid + h * 256;
            int ar = cc >> 2, acg = (cc & 3) << 3;
            int grow = row0 + ar;
            int ok = (grow < NN) ? 16 : 0;
            const __half* pa = ok ? (g_x + (size_t)grow * K + k0 + acg) : g_x;
            cpasync16(sb + ar * 80 + (acg << 1), pa, ok);
            int br = cc >> 4, bcg = (cc & 15) << 3;
            const __half* pb = wp + (size_t)(k0 + br) * 384 + col0 + bcg;
            cpasync16(sb + SB_OFF + br * 272 + (bcg << 1), pb, 16);
        }
        cp_commit();
    };

    issue(0);
    issue(1);

    const int arow = wr * 64 + (lane & 15);
    const int acol = (lane >> 4) << 3;
    const int krow = (lane & 15);
    const int ncll = wc * 32 + ((lane >> 4) << 3);

    for (int t = 0; t < nk; t++) {
        if (t + 1 < nk) cp_wait<1>(); else cp_wait<0>();
        __syncthreads();
        if (t + 2 < nk) issue(t + 2);
        uint32_t sb = smb + (t % 3) * STAGE_BYTES;
#pragma unroll
        for (int ks = 0; ks < 2; ks++) {
            uint32_t Ah[4][4], B[4][2];
#pragma unroll
            for (int mt = 0; mt < 4; mt++)
                ldsm4(Ah[mt], sb + (arow + mt * 16) * 80 + ((ks * 16 + acol) << 1));
            uint32_t bk = sb + SB_OFF + (ks * 16 + krow) * 272;
#pragma unroll
            for (int np = 0; np < 2; np++) {
                uint32_t r[4];
                ldsm4t(r, bk + ((ncll + np * 16) << 1));
                B[2*np][0] = r[0]; B[2*np][1] = r[1];
                B[2*np+1][0] = r[2]; B[2*np+1][1] = r[3];
            }
#pragma unroll
            for (int mt = 0; mt < 4; mt++)
#pragma unroll
                for (int nt = 0; nt < 4; nt++) mma16816f16(c[mt][nt], Ah[mt], B[nt]);
        }
    }

    // epilogue: fs columns -> g_fsh (fp16), fd columns -> g_fdh (fp16)
    int gid4 = lane >> 2, tig = lane & 3;
#pragma unroll
    for (int mt = 0; mt < 4; mt++) {
        int rg = row0 + wr * 64 + mt * 16 + gid4;
#pragma unroll
        for (int nt = 0; nt < 4; nt++) {
            int col = col0 + wc * 32 + nt * 8 + tig * 2;
            __half* base = (col < HD) ? (g_fsh + col) : (g_fdh + (col - HD));
            __half2 v0 = __float22half2_rn(make_float2(c[mt][nt][0], c[mt][nt][1]));
            __half2 v1 = __float22half2_rn(make_float2(c[mt][nt][2], c[mt][nt][3]));
            if (rg < NN)
                *reinterpret_cast<__half2*>(base + (size_t)rg * HD) = v0;
            if (rg + 8 < NN)
                *reinterpret_cast<__half2*>(base + (size_t)(rg + 8) * HD) = v1;
        }
    }
}

// ---------------- fused single-pass GATv2: one warp per node, 2-edge ILP ----------
// Frozen structure; fp16 gathers; half2-packed logit reduction; occ-4 bound.
__device__ __forceinline__ void edge_logits(
        int s, int lane,
        const float2* va, const float2* vd,
        float2* u, float* l) {
    const __half2* fs2 = reinterpret_cast<const __half2*>(g_fsh + (size_t)s * HD);
    u[0] = __half22float2(__ldg(fs2 + lane));
    u[1] = __half22float2(__ldg(fs2 + lane + 32));
    u[2] = __half22float2(__ldg(fs2 + lane + 64));
    float x, y;
    x = u[0].x + vd[0].x; x = x > 0.f ? x : NEG_GAT * x;
    y = u[0].y + vd[0].y; y = y > 0.f ? y : NEG_GAT * y;
    l[0] = x * va[0].x + y * va[0].y;
    x = u[1].x + vd[1].x; x = x > 0.f ? x : NEG_GAT * x;
    y = u[1].y + vd[1].y; y = y > 0.f ? y : NEG_GAT * y;
    l[1] = x * va[1].x + y * va[1].y;
    x = u[2].x + vd[2].x; x = x > 0.f ? x : NEG_GAT * x;
    y = u[2].y + vd[2].y; y = y > 0.f ? y : NEG_GAT * y;
    l[2] = x * va[2].x + y * va[2].y;
}

__global__ __launch_bounds__(256, 4) void gat_node_kernel(
        const float* __restrict__ attn,
        const float* __restrict__ bias,
        int do_pool, const int* __restrict__ gid) {
    int gw = (blockIdx.x * blockDim.x + threadIdx.x) >> 5;
    if (gw >= NN) return;
    int lane = threadIdx.x & 31;
    int n = gw;
    int p0 = __ldg(g_rowptr + n), p1 = __ldg(g_rowptr + n + 1);

    const float2* a2  = reinterpret_cast<const float2*>(attn);
    const __half2* fd2 = reinterpret_cast<const __half2*>(g_fdh + (size_t)n * HD);
    float2 va[3] = {a2[lane], a2[lane + 32], a2[lane + 64]};
    float2 vd[3] = {__half22float2(fd2[lane]),
                    __half22float2(fd2[lane + 32]),
                    __half22float2(fd2[lane + 64])};

    float den0 = 0.f, den1 = 0.f, den2 = 0.f;
    float2 acc0 = make_float2(0.f, 0.f), acc1 = acc0, acc2 = acc0;

    int p = p0;
    for (; p + 1 < p1; p += 2) {
        int sA = __ldg(g_esrc + p), sB = __ldg(g_esrc + p + 1);
        float2 uA[3], uB[3];
        float lA[3], lB[3];
        edge_logits(sA, lane, va, vd, uA, lA);
        edge_logits(sB, lane, va, vd, uB, lB);
        uint32_t pk[3];
#pragma unroll
        for (int h = 0; h < 3; h++) {
            __half2 v = __floats2half2_rn(lA[h], lB[h]);
            pk[h] = *reinterpret_cast<uint32_t*>(&v);
        }
#pragma unroll
        for (int o = 16; o; o >>= 1) {
#pragma unroll
            for (int h = 0; h < 3; h++) {
                uint32_t ot = __shfl_xor_sync(0xffffffffu, pk[h], o);
                __half2 s = __hadd2(*reinterpret_cast<__half2*>(&pk[h]),
                                    *reinterpret_cast<__half2*>(&ot));
                pk[h] = *reinterpret_cast<uint32_t*>(&s);
            }
        }
        float eA[3], eB[3];
#pragma unroll
        for (int h = 0; h < 3; h++) {
            float2 lf = __half22float2(*reinterpret_cast<__half2*>(&pk[h]));
            eA[h] = __expf(lf.x);
            eB[h] = __expf(lf.y);
        }
        den0 += eA[0] + eB[0]; den1 += eA[1] + eB[1]; den2 += eA[2] + eB[2];
        acc0.x += eA[0] * uA[0].x + eB[0] * uB[0].x; acc0.y += eA[0] * uA[0].y + eB[0] * uB[0].y;
        acc1.x += eA[1] * uA[1].x + eB[1] * uB[1].x; acc1.y += eA[1] * uA[1].y + eB[1] * uB[1].y;
        acc2.x += eA[2] * uA[2].x + eB[2] * uB[2].x; acc2.y += eA[2] * uA[2].y + eB[2] * uB[2].y;
    }
    if (p < p1) {
        int s = __ldg(g_esrc + p);
        float2 u[3];
        float l[3];
        edge_logits(s, lane, va, vd, u, l);
#pragma unroll
        for (int o = 16; o; o >>= 1) {
            l[0] += __shfl_xor_sync(0xffffffffu, l[0], o);
            l[1] += __shfl_xor_sync(0xffffffffu, l[1], o);
            l[2] += __shfl_xor_sync(0xffffffffu, l[2], o);
        }
        float e0 = __expf(l[0]), e1 = __expf(l[1]), e2 = __expf(l[2]);
        den0 += e0; den1 += e1; den2 += e2;
        acc0.x += e0 * u[0].x; acc0.y += e0 * u[0].y;
        acc1.x += e1 * u[1].x; acc1.y += e1 * u[1].y;
        acc2.x += e2 * u[2].x; acc2.y += e2 * u[2].y;
    }

    float i0 = 1.f / fmaxf(den0, 1e-9f);
    float i1 = 1.f / fmaxf(den1, 1e-9f);
    float i2 = 1.f / fmaxf(den2, 1e-9f);

    const float2* b2 = reinterpret_cast<const float2*>(bias);
    float2 w0 = b2[lane], w1 = b2[lane + 32], w2 = b2[lane + 64];
    float2 o0 = make_float2(acc0.x * i0 + w0.x, acc0.y * i0 + w0.y);
    float2 o1 = make_float2(acc1.x * i1 + w1.x, acc1.y * i1 + w1.y);
    float2 o2 = make_float2(acc2.x * i2 + w2.x, acc2.y * i2 + w2.y);

    if (!do_pool) {
        __half2* oh = reinterpret_cast<__half2*>(g_x + (size_t)n * HD);
        oh[lane]      = __float22half2_rn(o0);
        oh[lane + 32] = __float22half2_rn(o1);
        oh[lane + 64] = __float22half2_rn(o2);
    } else {
        int g = __ldg(gid + n);
        float vx = (o0.x + o1.x + o2.x) * (1.f / 3.f);
        float vy = (o0.y + o1.y + o2.y) * (1.f / 3.f);
        atomicAdd(&g_pool[g * DD + 2 * lane], vx);
        atomicAdd(&g_pool[g * DD + 2 * lane + 1], vy);
        if (lane == 0) atomicAdd(&g_cnt[g], 1.f);
    }
}

// ---------------- pattern branch + classifier head ----------------
__global__ void head_kernel(const float* __restrict__ p1, const float* __restrict__ p2,
                            const float* __restrict__ p3,
                            const float* __restrict__ Wex, const float* __restrict__ bex,
                            const float* __restrict__ Wpat, const float* __restrict__ bpat,
                            const float* __restrict__ Wc1, const float* __restrict__ bc1,
                            const float* __restrict__ Wc2, const float* __restrict__ bc2,
                            const float* __restrict__ Wc3, const float* __restrict__ bc3,
                            float* __restrict__ outp) {
    __shared__ float s_px[GG * 96];
    __shared__ float s_pat[GG * 64];
    int tid = threadIdx.x;

    for (int idx = tid; idx < GG * 96; idx += 256) {
        int g = idx / 96, j = idx % 96;
        const float* p = (j < 32) ? p1 : (j < 64 ? p2 : p3);
        int jj = j & 31;
        float s = bex[jj];
        for (int k = 0; k < PP; k++) s += p[g * PP + k] * Wex[k * 32 + jj];
        s_px[idx] = s;
    }
    __syncthreads();
    for (int idx = tid; idx < GG * 64; idx += 256) {
        int g = idx >> 6, j = idx & 63;
        float s = bpat[j];
        for (int k = 0; k < 96; k++) s += s_px[g * 96 + k] * Wpat[k * 64 + j];
        s_pat[idx] = s > 0.f ? s : NEG * s;
    }
    __syncthreads();
    for (int idx = tid; idx < GG * 64; idx += 256) {
        int g = idx >> 6, j = idx & 63;
        float s = bc1[j];
        float inv = 1.f / fmaxf(g_cnt[g], 1.f);
        for (int k = 0; k < 64; k++) s += (g_pool[g * 64 + k] * inv) * Wc1[k * 64 + j];
        for (int k = 0; k < 64; k++) s += s_pat[g * 64 + k] * Wc1[(64 + k) * 64 + j];
        s_px[idx] = s > 0.f ? s : NEG * s;
    }
    __syncthreads();
    for (int idx = tid; idx < GG * 32; idx += 256) {
        int g = idx >> 5, j = idx & 31;
        float s = bc2[j];
        for (int k = 0; k < 64; k++) s += s_px[g * 64 + k] * Wc2[k * 32 + j];
        s_px[4096 + idx] = s > 0.f ? s : NEG * s;
    }
    __syncthreads();
    for (int idx = tid; idx < GG * 2; idx += 256) {
        int g = idx >> 1, j = idx & 1;
        float s = bc3[j];
        for (int k = 0; k < 32; k++) s += s_px[4096 + g * 32 + k] * Wc3[k * 2 + j];
        outp[idx] = s;
    }
}

// ---------------- launcher ----------------
extern "C" void kernel_launch(void* const* d_in, const int* in_sizes, int n_in,
                              void* d_out, int out_size) {
    const float* x_in = (const float*)d_in[0];
    const int*   src  = (const int*)d_in[1];
    const int*   dst  = (const int*)d_in[2];
    const int*   gid  = (const int*)d_in[3];
    const float* p1   = (const float*)d_in[4];
    const float* p2   = (const float*)d_in[5];
    const float* p3   = (const float*)d_in[6];
    const float* W1s = (const float*)d_in[7],  *W1d = (const float*)d_in[8];
    const float* a1  = (const float*)d_in[9],  *b1  = (const float*)d_in[10];
    const float* W2s = (const float*)d_in[11], *W2d = (const float*)d_in[12];
    const float* a2  = (const float*)d_in[13], *b2  = (const float*)d_in[14];
    const float* W3s = (const float*)d_in[15], *W3d = (const float*)d_in[16];
    const float* a3  = (const float*)d_in[17], *b3  = (const float*)d_in[18];
    const float* Wex = (const float*)d_in[19], *bex = (const float*)d_in[20];
    const float* Wpat= (const float*)d_in[21], *bpat= (const float*)d_in[22];
    const float* Wc1 = (const float*)d_in[23], *bc1 = (const float*)d_in[24];
    const float* Wc2 = (const float*)d_in[25], *bc2 = (const float*)d_in[26];
    const float* Wc3 = (const float*)d_in[27], *bc3 = (const float*)d_in[28];

    cudaFuncSetAttribute(gemm_mma_kernel, cudaFuncAttributeMaxDynamicSharedMemorySize, GEMM_SMEM);

    dim3 gemm_grid((NN + 127) / 128, 3);       // (391, 3)
    int  node_blocks = (NN * 32 + 255) / 256;  // 6250
    size_t wstride = (size_t)HD * 384;

    // Launch order: profiled slot (4th) = gemm_mma (layer 1).
    init_zero_kernel<<<(NN + 255) / 256, 256>>>();                        // 1
    convert_x_kernel<<<(NN * F_IN / 4 + 255) / 256, 256>>>(x_in);         // 2
    convert_w_all_kernel<<<((F_IN + 2 * HD) * 384 + 255) / 256, 256>>>(
        W1s, W1d, W2s, W2d, W3s, W3d);                                    // 3
    gemm_mma_kernel<<<gemm_grid, 256, GEMM_SMEM>>>(F_IN, 0);              // 4 <- ncu slot

    // CSR build (needed only by gat kernels)
    hist_kernel<<<(EE + 255) / 256, 256>>>(dst);
    scan_kernel<<<1, 1024>>>();
    scatter_kernel<<<(EE + 255) / 256, 256>>>(src, dst);

    gat_node_kernel<<<node_blocks, 256>>>(a1, b1, 0, gid);

    // ---- Layer 2 (K = 192)
    gemm_mma_kernel<<<gemm_grid, 256, GEMM_SMEM>>>(HD, wstride);
    gat_node_kernel<<<node_blocks, 256>>>(a2, b2, 0, gid);

    // ---- Layer 3 (pooling fused)
    gemm_mma_kernel<<<gemm_grid, 256, GEMM_SMEM>>>(HD, 2 * wstride);
    gat_node_kernel<<<node_blocks, 256>>>(a3, b3, 1, gid);

    // ---- head
    head_kernel<<<1, 256>>>(p1, p2, p3, Wex, bex, Wpat, bpat,
                            Wc1, bc1, Wc2, bc2, Wc3, bc3, (float*)d_out);
}